// round 10
// baseline (speedup 1.0000x reference)
#include <cuda_runtime.h>
#include <cuda_fp16.h>
#include <math.h>

#define BB 8
#define SS 2048
#define DD 1024

static const float NEGV = -4294967296.0f; // float32(-(2^32)+1) rounds to -2^32

// scratch (allowed: __device__ globals)
__device__ __half g_x16[BB * SS * DD];
__device__ __half g_wq16[DD * DD];
__device__ __half g_wk16[DD * DD];
__device__ __half g_wv16[DD * DD];
__device__ float  g_q[BB * SS * DD];            // fp32 q for residual
__device__ __half g_q16[BB * SS * DD];
__device__ __half g_k16[BB * SS * DD];
__device__ __half g_v16[BB * SS * DD];
__device__ float  g_attn[(size_t)BB * SS * SS]; // fp32 scores
__device__ __half g_attn16[(size_t)BB * SS * SS];
__device__ float  g_masks[BB * SS];

// ---------------------------------------------------------------------------
__device__ __forceinline__ void mma_f16(float* d, const unsigned* a, const unsigned* b) {
    asm volatile(
        "mma.sync.aligned.m16n8k16.row.col.f32.f16.f16.f32 "
        "{%0,%1,%2,%3}, {%4,%5,%6,%7}, {%8,%9}, {%0,%1,%2,%3};\n"
        : "+f"(d[0]), "+f"(d[1]), "+f"(d[2]), "+f"(d[3])
        : "r"(a[0]), "r"(a[1]), "r"(a[2]), "r"(a[3]), "r"(b[0]), "r"(b[1]));
}
__device__ __forceinline__ void ldsm4(unsigned& r0, unsigned& r1, unsigned& r2, unsigned& r3,
                                      const void* p) {
    unsigned a = (unsigned)__cvta_generic_to_shared(p);
    asm volatile("ldmatrix.sync.aligned.m8n8.x4.shared.b16 {%0,%1,%2,%3}, [%4];\n"
                 : "=r"(r0), "=r"(r1), "=r"(r2), "=r"(r3) : "r"(a));
}
__device__ __forceinline__ void ldsm4t(unsigned& r0, unsigned& r1, unsigned& r2, unsigned& r3,
                                       const void* p) {
    unsigned a = (unsigned)__cvta_generic_to_shared(p);
    asm volatile("ldmatrix.sync.aligned.m8n8.x4.trans.shared.b16 {%0,%1,%2,%3}, [%4];\n"
                 : "=r"(r0), "=r"(r1), "=r"(r2), "=r"(r3) : "r"(a));
}
__device__ __forceinline__ void cp16(void* smem_dst, const void* gsrc) {
    unsigned s = (unsigned)__cvta_generic_to_shared(smem_dst);
    asm volatile("cp.async.cg.shared.global [%0], [%1], 16;\n" :: "r"(s), "l"(gsrc));
}
__device__ __forceinline__ void cp_commit() { asm volatile("cp.async.commit_group;\n"); }

#define A_STG 10240   // 256 * 40 halves
#define B_STG 5120    // max(128*40, 32*136) halves
#define NSTG 3        // cp.async ring depth

// ----------------------------------------------------------------------------
// FP16 tensor-core GEMM (f32 accum), 3-stage cp.async ring, ldmatrix frags.
// Block tile 256x128, BK=32, 256 threads (8 warps), warp tile 64x64 (2x4).
// MODE 0: C16 = relu(A @ B + bias) (+ optional fp32 copy)  B: [K][N] (trans)
// MODE 1: Cf  = mask_epilogue(A @ B^T / 32)                B: [N][K] (no-trans)
// MODE 2: Cf  = A @ B + resid                              B: [K][N] (trans)
// ----------------------------------------------------------------------------
template <int MODE>
__global__ __launch_bounds__(256) void gemm_h(
    const __half* __restrict__ Ab, const __half* __restrict__ Bb,
    const float* __restrict__ bias, const float* __restrict__ masks,
    const float* __restrict__ residb,
    float* __restrict__ Cfb, __half* __restrict__ C16b,
    int K, int lda, int ldb, int ldc,
    long bsA, long bsB, long bsC)
{
    const int z = blockIdx.z;
    const __half* A = Ab + (long)z * bsA;
    const __half* Bm = Bb + (long)z * bsB;
    float* Cf = Cfb ? (Cfb + (long)z * bsC) : nullptr;
    __half* C16 = C16b;

    extern __shared__ __half sm16[];
    __half* AsBase = sm16;
    __half* BsBase = sm16 + NSTG * A_STG;

    const int tid = threadIdx.x;
    const int lane = tid & 31;
    const int warp = tid >> 5;
    const int wm = warp >> 1;     // 0..3, 64 rows each
    const int wn = warp & 1;      // 0..1, 64 cols each
    const int gr = lane >> 2;     // 0..7
    const int tc = lane & 3;      // 0..3
    const int rowBase = blockIdx.y * 256;
    const int colBase = blockIdx.x * 128;

    // cp.async indices
    const int ar = tid >> 2;             // 0..63 (rows; A 4 u-steps, B-NT 2)
    const int ak = (tid & 3) << 3;       // k half-offset 0/8/16/24
    const int tr = tid >> 4;             // 0..15 (B-trans k-rows, 2 u-steps)
    const int tn = (tid & 15) << 3;      // n half-offset

    auto issue_tile = [&](int kt, int stg) {
        const int kBase = kt << 5;
        __half* As = AsBase + stg * A_STG;
        __half* Bs = BsBase + stg * B_STG;
#pragma unroll
        for (int u = 0; u < 4; u++) {
            int r = ar + u * 64;
            cp16(&As[r * 40 + ak], &A[(long)(rowBase + r) * lda + kBase + ak]);
        }
        if (MODE == 1) {
#pragma unroll
            for (int u = 0; u < 2; u++) {
                int r = ar + u * 64;
                cp16(&Bs[r * 40 + ak], &Bm[(long)(colBase + r) * ldb + kBase + ak]);
            }
        } else {
#pragma unroll
            for (int u = 0; u < 2; u++) {
                int r = tr + u * 16;
                cp16(&Bs[r * 136 + tn], &Bm[(long)(kBase + r) * ldb + colBase + tn]);
            }
        }
        cp_commit();
    };

    // ldmatrix per-lane offsets
    const int aRow = lane & 15;
    const int aCol = (lane >> 4) << 3;
    const int bnRow = (lane & 7) + ((lane & 16) ? 8 : 0);
    const int bnCol = (lane & 8);
    const int btRow = (lane & 7) + (lane & 8);
    const int btCol = ((lane & 16) ? 8 : 0);

    float acc[4][8][4];
#pragma unroll
    for (int mt = 0; mt < 4; mt++)
#pragma unroll
        for (int nt = 0; nt < 8; nt++)
#pragma unroll
            for (int i = 0; i < 4; i++) acc[mt][nt][i] = 0.0f;

    const int nkt = K >> 5;
    issue_tile(0, 0);
    issue_tile(1, 1);

    for (int kt = 0; kt < nkt; kt++) {
        const int stg = kt % NSTG;

        if (kt + 1 < nkt) asm volatile("cp.async.wait_group 1;\n" ::: "memory");
        else              asm volatile("cp.async.wait_group 0;\n" ::: "memory");
        __syncthreads();  // all warps done computing tile kt-1

        if (kt + 2 < nkt) issue_tile(kt + 2, (kt + 2) % NSTG);

        const __half* As = AsBase + stg * A_STG;
        const __half* Bs = BsBase + stg * B_STG;

#pragma unroll
        for (int ks = 0; ks < 2; ks++) {
            const int k0 = ks << 4;
            unsigned a[4][4], b[8][2];
#pragma unroll
            for (int mt = 0; mt < 4; mt++) {
                const int m0 = wm * 64 + mt * 16;
                ldsm4(a[mt][0], a[mt][1], a[mt][2], a[mt][3],
                      &As[(m0 + aRow) * 40 + k0 + aCol]);
            }
#pragma unroll
            for (int np = 0; np < 4; np++) {
                const int n0 = wn * 64 + np * 16;
                if (MODE == 1) {
                    ldsm4(b[2 * np][0], b[2 * np][1], b[2 * np + 1][0], b[2 * np + 1][1],
                          &Bs[(n0 + bnRow) * 40 + k0 + bnCol]);
                } else {
                    ldsm4t(b[2 * np][0], b[2 * np][1], b[2 * np + 1][0], b[2 * np + 1][1],
                           &Bs[(k0 + btRow) * 136 + n0 + btCol]);
                }
            }
#pragma unroll
            for (int mt = 0; mt < 4; mt++)
#pragma unroll
                for (int nt = 0; nt < 8; nt++)
                    mma_f16(acc[mt][nt], a[mt], b[nt]);
        }
    }

    // ---- epilogue ----
#pragma unroll
    for (int mt = 0; mt < 4; mt++) {
        const int r0 = rowBase + wm * 64 + mt * 16 + gr;  // and r0+8
#pragma unroll
        for (int nt = 0; nt < 8; nt++) {
            const int c0 = colBase + wn * 64 + nt * 8 + tc * 2;  // and c0+1
            float v0 = acc[mt][nt][0], v1 = acc[mt][nt][1];
            float v2 = acc[mt][nt][2], v3 = acc[mt][nt][3];

            if (MODE == 0) {
                float2 bj = *(const float2*)&bias[c0];
                v0 += bj.x; v1 += bj.y; v2 += bj.x; v3 += bj.y;
                v0 = v0 > 0.0f ? v0 : 0.0f;
                v1 = v1 > 0.0f ? v1 : 0.0f;
                v2 = v2 > 0.0f ? v2 : 0.0f;
                v3 = v3 > 0.0f ? v3 : 0.0f;
                *(__half2*)&C16[(long)r0 * ldc + c0] = __floats2half2_rn(v0, v1);
                *(__half2*)&C16[(long)(r0 + 8) * ldc + c0] = __floats2half2_rn(v2, v3);
                if (Cf) {
                    *(float2*)&Cf[(long)r0 * ldc + c0] = make_float2(v0, v1);
                    *(float2*)&Cf[(long)(r0 + 8) * ldc + c0] = make_float2(v2, v3);
                }
            } else if (MODE == 1) {
                float2 mv = *(const float2*)&masks[(long)z * SS + c0];
                v0 *= 0.03125f; v1 *= 0.03125f; v2 *= 0.03125f; v3 *= 0.03125f;
                if (mv.x == 0.0f) { v0 = NEGV; v2 = NEGV; }
                if (mv.y == 0.0f) { v1 = NEGV; v3 = NEGV; }
                *(float2*)&Cf[(long)r0 * ldc + c0] = make_float2(v0, v1);
                *(float2*)&Cf[(long)(r0 + 8) * ldc + c0] = make_float2(v2, v3);
            } else {
                const float* R = residb + (long)z * bsB;  // resid stride == bsB (SS*DD)
                float2 r1 = *(const float2*)&R[(long)r0 * ldc + c0];
                float2 r2 = *(const float2*)&R[(long)(r0 + 8) * ldc + c0];
                *(float2*)&Cf[(long)r0 * ldc + c0] = make_float2(v0 + r1.x, v1 + r1.y);
                *(float2*)&Cf[(long)(r0 + 8) * ldc + c0] = make_float2(v2 + r2.x, v3 + r2.y);
            }
        }
    }
}

// ----------------------------------------------------------------------------
__global__ __launch_bounds__(256) void cvt_f2h(const float* __restrict__ src,
                                              __half* __restrict__ dst, int n)
{
    int i = (blockIdx.x * blockDim.x + threadIdx.x) * 4;
    if (i >= n) return;
    float4 a = *(const float4*)&src[i];
    *(__half2*)&dst[i] = __floats2half2_rn(a.x, a.y);
    *(__half2*)&dst[i + 2] = __floats2half2_rn(a.z, a.w);
}

// ----------------------------------------------------------------------------
// Fused: masks[b,s] = sin(|sum_d x[b,s,d]|) AND x16 = fp16(x). One warp per row.
// ----------------------------------------------------------------------------
__global__ __launch_bounds__(256) void masks_cvt_k(const float* __restrict__ x)
{
    int warp = (blockIdx.x * blockDim.x + threadIdx.x) >> 5;
    int lane = threadIdx.x & 31;
    if (warp >= BB * SS) return;
    const float4* row = (const float4*)(x + (long)warp * DD);
    __half2* dst = (__half2*)(g_x16 + (long)warp * DD);
    float s = 0.0f;
#pragma unroll
    for (int i = 0; i < DD / 4 / 32; i++) {
        float4 v = row[lane + i * 32];
        s += v.x + v.y + v.z + v.w;
        dst[(lane + i * 32) * 2]     = __floats2half2_rn(v.x, v.y);
        dst[(lane + i * 32) * 2 + 1] = __floats2half2_rn(v.z, v.w);
    }
#pragma unroll
    for (int o = 16; o; o >>= 1) s += __shfl_xor_sync(0xFFFFFFFFu, s, o);
    if (lane == 0) g_masks[warp] = sinf(fabsf(s));
}

// ----------------------------------------------------------------------------
// Row softmax: fp32 scores -> fp16 attn (query-mask factor fused).
// ----------------------------------------------------------------------------
__global__ __launch_bounds__(256) void softmax_k()
{
    const long r = blockIdx.x;  // 0 .. B*S-1
    const float4* rv = (const float4*)(g_attn + r * (long)SS);
    __half2* ho = (__half2*)(g_attn16 + r * (long)SS);
    const int tid = threadIdx.x;
    const int lane = tid & 31;
    const int warp = tid >> 5;

    __shared__ float sredm[8];
    __shared__ float sreds[8];

    float4 v0 = rv[tid];
    float4 v1 = rv[tid + 256];

    float mx = fmaxf(fmaxf(fmaxf(v0.x, v0.y), fmaxf(v0.z, v0.w)),
                     fmaxf(fmaxf(v1.x, v1.y), fmaxf(v1.z, v1.w)));
#pragma unroll
    for (int o = 16; o; o >>= 1) mx = fmaxf(mx, __shfl_xor_sync(0xFFFFFFFFu, mx, o));
    if (lane == 0) sredm[warp] = mx;
    __syncthreads();
    mx = sredm[0];
#pragma unroll
    for (int i = 1; i < 8; i++) mx = fmaxf(mx, sredm[i]);

    v0.x = __expf(v0.x - mx); v0.y = __expf(v0.y - mx);
    v0.z = __expf(v0.z - mx); v0.w = __expf(v0.w - mx);
    v1.x = __expf(v1.x - mx); v1.y = __expf(v1.y - mx);
    v1.z = __expf(v1.z - mx); v1.w = __expf(v1.w - mx);

    float sm = v0.x + v0.y + v0.z + v0.w + v1.x + v1.y + v1.z + v1.w;
#pragma unroll
    for (int o = 16; o; o >>= 1) sm += __shfl_xor_sync(0xFFFFFFFFu, sm, o);
    if (lane == 0) sreds[warp] = sm;
    __syncthreads();
    sm = sreds[0];
#pragma unroll
    for (int i = 1; i < 8; i++) sm += sreds[i];

    const float inv = g_masks[r] / sm;  // normalize * query mask

    ho[2 * tid]       = __floats2half2_rn(v0.x * inv, v0.y * inv);
    ho[2 * tid + 1]   = __floats2half2_rn(v0.z * inv, v0.w * inv);
    ho[512 + 2 * tid] = __floats2half2_rn(v1.x * inv, v1.y * inv);
    ho[513 + 2 * tid] = __floats2half2_rn(v1.z * inv, v1.w * inv);
}

// ----------------------------------------------------------------------------
extern "C" void kernel_launch(void* const* d_in, const int* in_sizes, int n_in,
                              void* d_out, int out_size)
{
    const float* x  = (const float*)d_in[0];
    const float* Wq = (const float*)d_in[1];
    const float* bq = (const float*)d_in[2];
    const float* Wk = (const float*)d_in[3];
    const float* bk = (const float*)d_in[4];
    const float* Wv = (const float*)d_in[5];
    const float* bv = (const float*)d_in[6];
    float* out = (float*)d_out;

    __half *x16, *wq16, *wk16, *wv16, *q16, *k16, *v16, *attn16;
    float *q, *attn, *masks;
    cudaGetSymbolAddress((void**)&x16, g_x16);
    cudaGetSymbolAddress((void**)&wq16, g_wq16);
    cudaGetSymbolAddress((void**)&wk16, g_wk16);
    cudaGetSymbolAddress((void**)&wv16, g_wv16);
    cudaGetSymbolAddress((void**)&q, g_q);
    cudaGetSymbolAddress((void**)&q16, g_q16);
    cudaGetSymbolAddress((void**)&k16, g_k16);
    cudaGetSymbolAddress((void**)&v16, g_v16);
    cudaGetSymbolAddress((void**)&attn, g_attn);
    cudaGetSymbolAddress((void**)&attn16, g_attn16);
    cudaGetSymbolAddress((void**)&masks, g_masks);

    const int smemB = NSTG * (A_STG + B_STG) * sizeof(__half);  // 92160 bytes
    cudaFuncSetAttribute(gemm_h<0>, cudaFuncAttributeMaxDynamicSharedMemorySize, smemB);
    cudaFuncSetAttribute(gemm_h<1>, cudaFuncAttributeMaxDynamicSharedMemorySize, smemB);
    cudaFuncSetAttribute(gemm_h<2>, cudaFuncAttributeMaxDynamicSharedMemorySize, smemB);

    const long SD = (long)SS * DD;
    const long S2 = (long)SS * SS;

    // fp16 staging: x fused into masks kernel; weights separate
    masks_cvt_k<<<(BB * SS * 32 + 255) / 256, 256>>>(x);
    cvt_f2h<<<(DD * DD / 4 + 255) / 256, 256>>>(Wq, wq16, DD * DD);
    cvt_f2h<<<(DD * DD / 4 + 255) / 256, 256>>>(Wk, wk16, DD * DD);
    cvt_f2h<<<(DD * DD / 4 + 255) / 256, 256>>>(Wv, wv16, DD * DD);

    // QKV projections: relu(x @ W + b) -> fp16 (+ fp32 q for residual)
    dim3 gp(DD / 128, (BB * SS) / 256, 1);
    gemm_h<0><<<gp, 256, smemB>>>(x16, wq16, bq, nullptr, nullptr, q, q16,
                                  DD, DD, DD, DD, 0, 0, 0);
    gemm_h<0><<<gp, 256, smemB>>>(x16, wk16, bk, nullptr, nullptr, nullptr, k16,
                                  DD, DD, DD, DD, 0, 0, 0);
    gemm_h<0><<<gp, 256, smemB>>>(x16, wv16, bv, nullptr, nullptr, nullptr, v16,
                                  DD, DD, DD, DD, 0, 0, 0);

    // scores = q @ k^T / 32, key mask -> fp32 g_attn  (per batch)
    gemm_h<1><<<dim3(SS / 128, SS / 256, BB), 256, smemB>>>(
        q16, k16, nullptr, masks, nullptr, attn, nullptr,
        DD, DD, DD, SS, SD, SD, S2);

    // softmax + query mask -> fp16 attn16
    softmax_k<<<BB * SS, 256>>>();

    // out = attn @ v + q  (per batch)
    gemm_h<2><<<dim3(DD / 128, SS / 256, BB), 256, smemB>>>(
        attn16, v16, nullptr, nullptr, q, out, nullptr,
        SS, SS, DD, DD, S2, SD, SD);
}

// round 11
// speedup vs baseline: 1.2419x; 1.2419x over previous
#include <cuda_runtime.h>
#include <cuda_fp16.h>
#include <math.h>

#define BB 8
#define SS 2048
#define DD 1024

static const float NEGV = -4294967296.0f; // float32(-(2^32)+1) rounds to -2^32

// scratch (allowed: __device__ globals)
__device__ __half g_x16[BB * SS * DD];
__device__ __half g_wq16[DD * DD];
__device__ __half g_wk16[DD * DD];
__device__ __half g_wv16[DD * DD];
__device__ float  g_q[BB * SS * DD];            // fp32 q for residual
__device__ __half g_q16[BB * SS * DD];
__device__ __half g_k16[BB * SS * DD];
__device__ __half g_v16[BB * SS * DD];
__device__ float  g_attn[(size_t)BB * SS * SS]; // fp32 scores
__device__ __half g_attn16[(size_t)BB * SS * SS];
__device__ float  g_masks[BB * SS];

// ---------------------------------------------------------------------------
__device__ __forceinline__ void mma_f16(float* d, const unsigned* a, const unsigned* b) {
    asm volatile(
        "mma.sync.aligned.m16n8k16.row.col.f32.f16.f16.f32 "
        "{%0,%1,%2,%3}, {%4,%5,%6,%7}, {%8,%9}, {%0,%1,%2,%3};\n"
        : "+f"(d[0]), "+f"(d[1]), "+f"(d[2]), "+f"(d[3])
        : "r"(a[0]), "r"(a[1]), "r"(a[2]), "r"(a[3]), "r"(b[0]), "r"(b[1]));
}
__device__ __forceinline__ void ldsm4(unsigned& r0, unsigned& r1, unsigned& r2, unsigned& r3,
                                      const void* p) {
    unsigned a = (unsigned)__cvta_generic_to_shared(p);
    asm volatile("ldmatrix.sync.aligned.m8n8.x4.shared.b16 {%0,%1,%2,%3}, [%4];\n"
                 : "=r"(r0), "=r"(r1), "=r"(r2), "=r"(r3) : "r"(a));
}
__device__ __forceinline__ void ldsm4t(unsigned& r0, unsigned& r1, unsigned& r2, unsigned& r3,
                                       const void* p) {
    unsigned a = (unsigned)__cvta_generic_to_shared(p);
    asm volatile("ldmatrix.sync.aligned.m8n8.x4.trans.shared.b16 {%0,%1,%2,%3}, [%4];\n"
                 : "=r"(r0), "=r"(r1), "=r"(r2), "=r"(r3) : "r"(a));
}
__device__ __forceinline__ void cp16(void* smem_dst, const void* gsrc) {
    unsigned s = (unsigned)__cvta_generic_to_shared(smem_dst);
    asm volatile("cp.async.cg.shared.global [%0], [%1], 16;\n" :: "r"(s), "l"(gsrc));
}
__device__ __forceinline__ void cp_commit() { asm volatile("cp.async.commit_group;\n"); }

#define STG_H 5120  // per-stage smem halves (covers 128*40 and 32*136)
#define NSTG 3      // cp.async ring depth

// ----------------------------------------------------------------------------
// FP16 tensor-core GEMM (f32 accum), 3-stage cp.async ring, ldmatrix frags.
// Block tile 128x128, BK=32, 256 threads (8 warps), warp tile 32x64.
// MODE 0: C16 = relu(A @ B + bias) (+ optional fp32 copy)  B: [K][N] (trans)
// MODE 1: Cf  = mask_epilogue(A @ B^T / 32)                B: [N][K] (no-trans)
// MODE 2: Cf  = A @ B + resid                              B: [K][N] (trans)
// ----------------------------------------------------------------------------
template <int MODE>
__global__ __launch_bounds__(256, 2) void gemm_h(
    const __half* __restrict__ Ab, const __half* __restrict__ Bb,
    const float* __restrict__ bias, const float* __restrict__ masks,
    const float* __restrict__ residb,
    float* __restrict__ Cfb, __half* __restrict__ C16b,
    int K, int lda, int ldb, int ldc,
    long bsA, long bsB, long bsC)
{
    const int z = blockIdx.z;
    const __half* A = Ab + (long)z * bsA;
    const __half* Bm = Bb + (long)z * bsB;
    float* Cf = Cfb ? (Cfb + (long)z * bsC) : nullptr;
    __half* C16 = C16b;

    extern __shared__ __half sm16[];
    __half* AsBase = sm16;
    __half* BsBase = sm16 + NSTG * STG_H;

    const int tid = threadIdx.x;
    const int lane = tid & 31;
    const int warp = tid >> 5;
    const int wm = warp & 3;      // 0..3, 32 rows
    const int wn = warp >> 2;     // 0..1, 64 cols
    const int gr = lane >> 2;     // 0..7
    const int tc = lane & 3;      // 0..3
    const int rowBase = blockIdx.y * 128;
    const int colBase = blockIdx.x * 128;

    // cp.async indices
    const int ar = tid >> 2;             // 0..63 (A & B-NT rows, 2 u-steps of 64)
    const int ak = (tid & 3) << 3;       // k half-offset 0/8/16/24
    const int tr = tid >> 4;             // 0..15 (B-trans rows, 2 u-steps of 16)
    const int tn = (tid & 15) << 3;      // n half-offset

    auto issue_tile = [&](int kt, int stg) {
        const int kBase = kt << 5;
        __half* As = AsBase + stg * STG_H;
        __half* Bs = BsBase + stg * STG_H;
#pragma unroll
        for (int u = 0; u < 2; u++) {
            int r = ar + u * 64;
            cp16(&As[r * 40 + ak], &A[(long)(rowBase + r) * lda + kBase + ak]);
        }
        if (MODE == 1) {
#pragma unroll
            for (int u = 0; u < 2; u++) {
                int r = ar + u * 64;
                cp16(&Bs[r * 40 + ak], &Bm[(long)(colBase + r) * ldb + kBase + ak]);
            }
        } else {
#pragma unroll
            for (int u = 0; u < 2; u++) {
                int r = tr + u * 16;
                cp16(&Bs[r * 136 + tn], &Bm[(long)(kBase + r) * ldb + colBase + tn]);
            }
        }
        cp_commit();
    };

    // ldmatrix per-lane offsets
    const int aRow = lane & 15;
    const int aCol = (lane >> 4) << 3;
    const int bnRow = (lane & 7) + ((lane & 16) ? 8 : 0);
    const int bnCol = (lane & 8);
    const int btRow = (lane & 7) + (lane & 8);
    const int btCol = ((lane & 16) ? 8 : 0);

    float acc[2][8][4];
#pragma unroll
    for (int mt = 0; mt < 2; mt++)
#pragma unroll
        for (int nt = 0; nt < 8; nt++)
#pragma unroll
            for (int i = 0; i < 4; i++) acc[mt][nt][i] = 0.0f;

    const int nkt = K >> 5;
    issue_tile(0, 0);
    issue_tile(1, 1);

    for (int kt = 0; kt < nkt; kt++) {
        const int stg = kt % NSTG;

        // tile kt ready when <=1 group outstanding (the kt+1 prefetch)
        if (kt + 1 < nkt) asm volatile("cp.async.wait_group 1;\n" ::: "memory");
        else              asm volatile("cp.async.wait_group 0;\n" ::: "memory");
        __syncthreads();  // also: all warps are done computing tile kt-1

        // prefetch kt+2 into buffer (kt+2)%3 == (kt-1)%3 (free: see barrier above)
        if (kt + 2 < nkt) issue_tile(kt + 2, (kt + 2) % NSTG);

        const __half* As = AsBase + stg * STG_H;
        const __half* Bs = BsBase + stg * STG_H;

#pragma unroll
        for (int ks = 0; ks < 2; ks++) {
            const int k0 = ks << 4;
            unsigned a[2][4], b[8][2];
#pragma unroll
            for (int mt = 0; mt < 2; mt++) {
                const int m0 = wm * 32 + mt * 16;
                ldsm4(a[mt][0], a[mt][1], a[mt][2], a[mt][3],
                      &As[(m0 + aRow) * 40 + k0 + aCol]);
            }
#pragma unroll
            for (int np = 0; np < 4; np++) {
                const int n0 = wn * 64 + np * 16;
                if (MODE == 1) {
                    ldsm4(b[2 * np][0], b[2 * np][1], b[2 * np + 1][0], b[2 * np + 1][1],
                          &Bs[(n0 + bnRow) * 40 + k0 + bnCol]);
                } else {
                    ldsm4t(b[2 * np][0], b[2 * np][1], b[2 * np + 1][0], b[2 * np + 1][1],
                           &Bs[(k0 + btRow) * 136 + n0 + btCol]);
                }
            }
#pragma unroll
            for (int mt = 0; mt < 2; mt++)
#pragma unroll
                for (int nt = 0; nt < 8; nt++)
                    mma_f16(acc[mt][nt], a[mt], b[nt]);
        }
    }

    // ---- epilogue ----
#pragma unroll
    for (int mt = 0; mt < 2; mt++) {
        const int r0 = rowBase + wm * 32 + mt * 16 + gr;  // and r0+8
#pragma unroll
        for (int nt = 0; nt < 8; nt++) {
            const int c0 = colBase + wn * 64 + nt * 8 + tc * 2;  // and c0+1
            float v0 = acc[mt][nt][0], v1 = acc[mt][nt][1];
            float v2 = acc[mt][nt][2], v3 = acc[mt][nt][3];

            if (MODE == 0) {
                float2 bj = *(const float2*)&bias[c0];
                v0 += bj.x; v1 += bj.y; v2 += bj.x; v3 += bj.y;
                v0 = v0 > 0.0f ? v0 : 0.0f;
                v1 = v1 > 0.0f ? v1 : 0.0f;
                v2 = v2 > 0.0f ? v2 : 0.0f;
                v3 = v3 > 0.0f ? v3 : 0.0f;
                *(__half2*)&C16[(long)r0 * ldc + c0] = __floats2half2_rn(v0, v1);
                *(__half2*)&C16[(long)(r0 + 8) * ldc + c0] = __floats2half2_rn(v2, v3);
                if (Cf) {
                    *(float2*)&Cf[(long)r0 * ldc + c0] = make_float2(v0, v1);
                    *(float2*)&Cf[(long)(r0 + 8) * ldc + c0] = make_float2(v2, v3);
                }
            } else if (MODE == 1) {
                float2 mv = *(const float2*)&masks[(long)z * SS + c0];
                v0 *= 0.03125f; v1 *= 0.03125f; v2 *= 0.03125f; v3 *= 0.03125f;
                if (mv.x == 0.0f) { v0 = NEGV; v2 = NEGV; }
                if (mv.y == 0.0f) { v1 = NEGV; v3 = NEGV; }
                *(float2*)&Cf[(long)r0 * ldc + c0] = make_float2(v0, v1);
                *(float2*)&Cf[(long)(r0 + 8) * ldc + c0] = make_float2(v2, v3);
            } else {
                const float* R = residb + (long)z * bsB;  // resid stride == bsB (SS*DD)
                float2 r1 = *(const float2*)&R[(long)r0 * ldc + c0];
                float2 r2 = *(const float2*)&R[(long)(r0 + 8) * ldc + c0];
                *(float2*)&Cf[(long)r0 * ldc + c0] = make_float2(v0 + r1.x, v1 + r1.y);
                *(float2*)&Cf[(long)(r0 + 8) * ldc + c0] = make_float2(v2 + r2.x, v3 + r2.y);
            }
        }
    }
}

// ----------------------------------------------------------------------------
__global__ __launch_bounds__(256) void cvt_f2h(const float* __restrict__ src,
                                              __half* __restrict__ dst, int n)
{
    int i = (blockIdx.x * blockDim.x + threadIdx.x) * 4;
    if (i >= n) return;
    float4 a = *(const float4*)&src[i];
    *(__half2*)&dst[i] = __floats2half2_rn(a.x, a.y);
    *(__half2*)&dst[i + 2] = __floats2half2_rn(a.z, a.w);
}

// ----------------------------------------------------------------------------
// Fused: masks[b,s] = sin(|sum_d x[b,s,d]|) AND x16 = fp16(x). One warp per row.
// ----------------------------------------------------------------------------
__global__ __launch_bounds__(256) void masks_cvt_k(const float* __restrict__ x)
{
    int warp = (blockIdx.x * blockDim.x + threadIdx.x) >> 5;
    int lane = threadIdx.x & 31;
    if (warp >= BB * SS) return;
    const float4* row = (const float4*)(x + (long)warp * DD);
    __half2* dst = (__half2*)(g_x16 + (long)warp * DD);
    float s = 0.0f;
#pragma unroll
    for (int i = 0; i < DD / 4 / 32; i++) {
        float4 v = row[lane + i * 32];
        s += v.x + v.y + v.z + v.w;
        dst[(lane + i * 32) * 2]     = __floats2half2_rn(v.x, v.y);
        dst[(lane + i * 32) * 2 + 1] = __floats2half2_rn(v.z, v.w);
    }
#pragma unroll
    for (int o = 16; o; o >>= 1) s += __shfl_xor_sync(0xFFFFFFFFu, s, o);
    if (lane == 0) g_masks[warp] = sinf(fabsf(s));
}

// ----------------------------------------------------------------------------
// Row softmax: fp32 scores -> fp16 attn (query-mask factor fused).
// ----------------------------------------------------------------------------
__global__ __launch_bounds__(256) void softmax_k()
{
    const long r = blockIdx.x;  // 0 .. B*S-1
    const float4* rv = (const float4*)(g_attn + r * (long)SS);
    __half2* ho = (__half2*)(g_attn16 + r * (long)SS);
    const int tid = threadIdx.x;
    const int lane = tid & 31;
    const int warp = tid >> 5;

    __shared__ float sredm[8];
    __shared__ float sreds[8];

    float4 v0 = rv[tid];
    float4 v1 = rv[tid + 256];

    float mx = fmaxf(fmaxf(fmaxf(v0.x, v0.y), fmaxf(v0.z, v0.w)),
                     fmaxf(fmaxf(v1.x, v1.y), fmaxf(v1.z, v1.w)));
#pragma unroll
    for (int o = 16; o; o >>= 1) mx = fmaxf(mx, __shfl_xor_sync(0xFFFFFFFFu, mx, o));
    if (lane == 0) sredm[warp] = mx;
    __syncthreads();
    mx = sredm[0];
#pragma unroll
    for (int i = 1; i < 8; i++) mx = fmaxf(mx, sredm[i]);

    v0.x = __expf(v0.x - mx); v0.y = __expf(v0.y - mx);
    v0.z = __expf(v0.z - mx); v0.w = __expf(v0.w - mx);
    v1.x = __expf(v1.x - mx); v1.y = __expf(v1.y - mx);
    v1.z = __expf(v1.z - mx); v1.w = __expf(v1.w - mx);

    float sm = v0.x + v0.y + v0.z + v0.w + v1.x + v1.y + v1.z + v1.w;
#pragma unroll
    for (int o = 16; o; o >>= 1) sm += __shfl_xor_sync(0xFFFFFFFFu, sm, o);
    if (lane == 0) sreds[warp] = sm;
    __syncthreads();
    sm = sreds[0];
#pragma unroll
    for (int i = 1; i < 8; i++) sm += sreds[i];

    const float inv = g_masks[r] / sm;  // normalize * query mask

    ho[2 * tid]       = __floats2half2_rn(v0.x * inv, v0.y * inv);
    ho[2 * tid + 1]   = __floats2half2_rn(v0.z * inv, v0.w * inv);
    ho[512 + 2 * tid] = __floats2half2_rn(v1.x * inv, v1.y * inv);
    ho[513 + 2 * tid] = __floats2half2_rn(v1.z * inv, v1.w * inv);
}

// ----------------------------------------------------------------------------
extern "C" void kernel_launch(void* const* d_in, const int* in_sizes, int n_in,
                              void* d_out, int out_size)
{
    const float* x  = (const float*)d_in[0];
    const float* Wq = (const float*)d_in[1];
    const float* bq = (const float*)d_in[2];
    const float* Wk = (const float*)d_in[3];
    const float* bk = (const float*)d_in[4];
    const float* Wv = (const float*)d_in[5];
    const float* bv = (const float*)d_in[6];
    float* out = (float*)d_out;

    __half *x16, *wq16, *wk16, *wv16, *q16, *k16, *v16, *attn16;
    float *q, *attn, *masks;
    cudaGetSymbolAddress((void**)&x16, g_x16);
    cudaGetSymbolAddress((void**)&wq16, g_wq16);
    cudaGetSymbolAddress((void**)&wk16, g_wk16);
    cudaGetSymbolAddress((void**)&wv16, g_wv16);
    cudaGetSymbolAddress((void**)&q, g_q);
    cudaGetSymbolAddress((void**)&q16, g_q16);
    cudaGetSymbolAddress((void**)&k16, g_k16);
    cudaGetSymbolAddress((void**)&v16, g_v16);
    cudaGetSymbolAddress((void**)&attn, g_attn);
    cudaGetSymbolAddress((void**)&attn16, g_attn16);
    cudaGetSymbolAddress((void**)&masks, g_masks);

    const int smemB = 2 * NSTG * STG_H * sizeof(__half);  // 61440 bytes
    cudaFuncSetAttribute(gemm_h<0>, cudaFuncAttributeMaxDynamicSharedMemorySize, smemB);
    cudaFuncSetAttribute(gemm_h<1>, cudaFuncAttributeMaxDynamicSharedMemorySize, smemB);
    cudaFuncSetAttribute(gemm_h<2>, cudaFuncAttributeMaxDynamicSharedMemorySize, smemB);

    const long SD = (long)SS * DD;
    const long S2 = (long)SS * SS;

    // fp16 staging: x fused into masks kernel; weights separate
    masks_cvt_k<<<(BB * SS * 32 + 255) / 256, 256>>>(x);
    cvt_f2h<<<(DD * DD / 4 + 255) / 256, 256>>>(Wq, wq16, DD * DD);
    cvt_f2h<<<(DD * DD / 4 + 255) / 256, 256>>>(Wk, wk16, DD * DD);
    cvt_f2h<<<(DD * DD / 4 + 255) / 256, 256>>>(Wv, wv16, DD * DD);

    // QKV projections: relu(x @ W + b) -> fp16 (+ fp32 q for residual)
    dim3 gp(DD / 128, (BB * SS) / 128, 1);
    gemm_h<0><<<gp, 256, smemB>>>(x16, wq16, bq, nullptr, nullptr, q, q16,
                                  DD, DD, DD, DD, 0, 0, 0);
    gemm_h<0><<<gp, 256, smemB>>>(x16, wk16, bk, nullptr, nullptr, nullptr, k16,
                                  DD, DD, DD, DD, 0, 0, 0);
    gemm_h<0><<<gp, 256, smemB>>>(x16, wv16, bv, nullptr, nullptr, nullptr, v16,
                                  DD, DD, DD, DD, 0, 0, 0);

    // scores = q @ k^T / 32, key mask -> fp32 g_attn  (per batch)
    gemm_h<1><<<dim3(SS / 128, SS / 128, BB), 256, smemB>>>(
        q16, k16, nullptr, masks, nullptr, attn, nullptr,
        DD, DD, DD, SS, SD, SD, S2);

    // softmax + query mask -> fp16 attn16
    softmax_k<<<BB * SS, 256>>>();

    // out = attn @ v + q  (per batch)
    gemm_h<2><<<dim3(DD / 128, SS / 128, BB), 256, smemB>>>(
        attn16, v16, nullptr, nullptr, q, out, nullptr,
        SS, SS, DD, DD, S2, SD, SD);
}